// round 1
// baseline (speedup 1.0000x reference)
#include <cuda_runtime.h>

// 3D trilinear grid_sample, align_corners=False, padding_mode='border'
// image: [B, C, D, H, W] float32
// flow:  [B, 3, D, H, W] float32 (x,y,z displacements in voxels)
// out:   [B, C, D, H, W] float32

#define B_ 2
#define C_ 2
#define D_ 128
#define H_ 128
#define W_ 128

__global__ __launch_bounds__(256) void warp3d_kernel(
    const float* __restrict__ image,
    const float* __restrict__ flow,
    float* __restrict__ out)
{
    constexpr int N = D_ * H_ * W_;            // voxels per (b, channel/flow-comp)
    int tid = blockIdx.x * blockDim.x + threadIdx.x;
    if (tid >= B_ * N) return;

    int b = tid / N;
    int p = tid - b * N;                        // z*H*W + y*W + x
    int x = p & (W_ - 1);
    int y = (p >> 7) & (H_ - 1);
    int z = p >> 14;

    const float* fb = flow + (size_t)b * 3 * N;
    float fx = __ldg(fb + p);
    float fy = __ldg(fb + N + p);
    float fz = __ldg(fb + 2 * N + p);

    // ix = (x + fx) * W/(W-1) - 0.5, clamped to [0, W-1]
    constexpr float sW = (float)W_ / (float)(W_ - 1);
    constexpr float sH = (float)H_ / (float)(H_ - 1);
    constexpr float sD = (float)D_ / (float)(D_ - 1);

    float ix = fminf(fmaxf(fmaf((float)x + fx, sW, -0.5f), 0.0f), (float)(W_ - 1));
    float iy = fminf(fmaxf(fmaf((float)y + fy, sH, -0.5f), 0.0f), (float)(H_ - 1));
    float iz = fminf(fmaxf(fmaf((float)z + fz, sD, -0.5f), 0.0f), (float)(D_ - 1));

    float x0f = floorf(ix), y0f = floorf(iy), z0f = floorf(iz);
    float tx = ix - x0f, ty = iy - y0f, tz = iz - z0f;

    int x0 = (int)x0f, y0 = (int)y0f, z0 = (int)z0f;
    int x1 = min(x0 + 1, W_ - 1);
    int y1 = min(y0 + 1, H_ - 1);
    int z1 = min(z0 + 1, D_ - 1);

    // 8 corner flat offsets (shared by both channels)
    int zy00 = (z0 * H_ + y0) * W_;
    int zy01 = (z0 * H_ + y1) * W_;
    int zy10 = (z1 * H_ + y0) * W_;
    int zy11 = (z1 * H_ + y1) * W_;

    int o000 = zy00 + x0, o001 = zy00 + x1;
    int o010 = zy01 + x0, o011 = zy01 + x1;
    int o100 = zy10 + x0, o101 = zy10 + x1;
    int o110 = zy11 + x0, o111 = zy11 + x1;

    float wx0 = 1.0f - tx, wx1 = tx;
    float wy0 = 1.0f - ty, wy1 = ty;
    float wz0 = 1.0f - tz, wz1 = tz;

    float w000 = wz0 * wy0 * wx0;
    float w001 = wz0 * wy0 * wx1;
    float w010 = wz0 * wy1 * wx0;
    float w011 = wz0 * wy1 * wx1;
    float w100 = wz1 * wy0 * wx0;
    float w101 = wz1 * wy0 * wx1;
    float w110 = wz1 * wy1 * wx0;
    float w111 = wz1 * wy1 * wx1;

    #pragma unroll
    for (int c = 0; c < C_; c++) {
        const float* img = image + ((size_t)b * C_ + c) * N;
        float acc = __ldg(img + o000) * w000
                  + __ldg(img + o001) * w001
                  + __ldg(img + o010) * w010
                  + __ldg(img + o011) * w011
                  + __ldg(img + o100) * w100
                  + __ldg(img + o101) * w101
                  + __ldg(img + o110) * w110
                  + __ldg(img + o111) * w111;
        out[((size_t)b * C_ + c) * N + p] = acc;
    }
}

extern "C" void kernel_launch(void* const* d_in, const int* in_sizes, int n_in,
                              void* d_out, int out_size)
{
    const float* image = (const float*)d_in[0];
    const float* flow  = (const float*)d_in[1];
    float* out = (float*)d_out;

    constexpr int total = B_ * D_ * H_ * W_;
    dim3 block(256);
    dim3 grid((total + 255) / 256);
    warp3d_kernel<<<grid, block>>>(image, flow, out);
}